// round 1
// baseline (speedup 1.0000x reference)
#include <cuda_runtime.h>

// CapsuleBlock: B=64, N=2048, D_in=8, K(N_out)=16, O(D_out)=16, 3 routing iters.
// Strategy: never materialize hats (134MB). Recompute per routing pass from
// x (4MB) + W (16MB), each block owning a disjoint n-chunk. Cross-block
// reduction of s via per-block partials + tiny squash kernel.
// Inner math uses packed f32x2 FMA (Blackwell FFMA2) over D_out pairs.

#define NBLK   152
#define CHUNK  14          // NBLK*CHUNK = 2128 >= 2048
#define THREADS 512        // thread = (b, kp): b=tid>>3 (64), kp=tid&7 (8 k-pairs)

__device__ float g_part[(size_t)NBLK * 16384];  // per-block partial s [blk][b][k][o]
__device__ float g_route[16384];                // routing vector [b][k][o]

typedef unsigned long long ull;

__device__ __forceinline__ ull pack2(float v) {
    ull r; asm("mov.b64 %0, {%1, %1};" : "=l"(r) : "f"(v)); return r;
}
__device__ __forceinline__ ull fma2(ull a, ull b, ull c) {
    ull d; asm("fma.rn.f32x2 %0, %1, %2, %3;" : "=l"(d) : "l"(a), "l"(b), "l"(c)); return d;
}
__device__ __forceinline__ ull mul2(ull a, ull b) {
    ull d; asm("mul.rn.f32x2 %0, %1, %2;" : "=l"(d) : "l"(a), "l"(b)); return d;
}
__device__ __forceinline__ float2 unpack2(ull v) {
    float2 r; asm("mov.b64 {%0, %1}, %2;" : "=f"(r.x), "=f"(r.y) : "l"(v)); return r;
}

// FIRST=true: routing iter 0 (uniform c=1/16, folded into squash scale) —
// accumulate s += x*W directly, no per-n hats.
// FIRST=false: per n compute hats, bias = <hats, route>, softmax over 16 k
// (warp shuffles within the 8-lane kp group), acc += c*hats.
template <bool FIRST>
__global__ void __launch_bounds__(THREADS, 1)
pass_kernel(const float* __restrict__ x, const float* __restrict__ W) {
    // Ws layout: [d][opair][k] as float2 (o even, o odd). A warp's 8 kp lanes
    // do LDS.128 at 16B stride -> one conflict-free 128B phase, 4-way b-broadcast.
    __shared__ __align__(16) float2 Ws[8][8][16];        // 8 KB
    __shared__ float xs[CHUNK][64][8];                   // 28 KB

    const int tid = threadIdx.x;
    const int b  = tid >> 3;
    const int kp = tid & 7;
    const int n0 = blockIdx.x * CHUNK;
    int nmax = 2048 - n0; if (nmax > CHUNK) nmax = CHUNK;   // may be <= 0 (tail blocks)

    // ---- stage x[:, n0:n0+nmax, :] into smem ----
    for (int i = tid; i < nmax * 128; i += THREADS) {
        int ln = i >> 7, r = i & 127, bb = r >> 1, dq = r & 1;
        float4 v = *(const float4*)(x + ((size_t)bb * 2048 + (size_t)(n0 + ln)) * 8 + dq * 4);
        *(float4*)(&xs[ln][bb][dq * 4]) = v;
    }

    // ---- W prefetch mapping: thread -> (k, d, o-quad) of one 8KB W[n] row ----
    const int wk = tid & 15, wt = tid >> 4, wd = wt >> 2, woq = wt & 3;
    const size_t woff = (size_t)wk * 128 + (size_t)wd * 16 + (size_t)woq * 4;
    float4 wreg = make_float4(0.f, 0.f, 0.f, 0.f);
    if (nmax > 0) wreg = *(const float4*)(W + (size_t)n0 * 2048 + woff);

    ull acc0[8], acc1[8];
#pragma unroll
    for (int op = 0; op < 8; op++) { acc0[op] = 0ull; acc1[op] = 0ull; }

    // routing vector for this thread's (b, k0=2kp, k1=2kp+1), held in regs
    ull r0[8], r1[8];
    if (!FIRST) {
        const ull* rp = (const ull*)g_route;  // pairs of consecutive o
#pragma unroll
        for (int op = 0; op < 8; op++) {
            r0[op] = rp[((size_t)b * 16 + 2 * kp) * 8 + op];
            r1[op] = rp[((size_t)b * 16 + 2 * kp + 1) * 8 + op];
        }
    }

    for (int ln = 0; ln < nmax; ln++) {
        // stage W[n] (transposed) — wreg was prefetched one iteration ago
        Ws[wd][2 * woq    ][wk] = make_float2(wreg.x, wreg.y);
        Ws[wd][2 * woq + 1][wk] = make_float2(wreg.z, wreg.w);
        __syncthreads();
        if (ln + 1 < nmax)
            wreg = *(const float4*)(W + (size_t)(n0 + ln + 1) * 2048 + woff);

        ull h0[8], h1[8];
#pragma unroll
        for (int d = 0; d < 8; d++) {
            ull xd = pack2(xs[ln][b][d]);
#pragma unroll
            for (int op = 0; op < 8; op++) {
                ulonglong2 w = *(const ulonglong2*)&Ws[d][op][2 * kp];
                if (FIRST) {
                    acc0[op] = fma2(xd, w.x, acc0[op]);
                    acc1[op] = fma2(xd, w.y, acc1[op]);
                } else if (d == 0) {
                    h0[op] = mul2(xd, w.x);
                    h1[op] = mul2(xd, w.y);
                } else {
                    h0[op] = fma2(xd, w.x, h0[op]);
                    h1[op] = fma2(xd, w.y, h1[op]);
                }
            }
        }

        if (!FIRST) {
            // bias_k = sum_o hats[k][o] * route[k][o]
            ull t0 = mul2(h0[0], r0[0]);
            ull t1 = mul2(h1[0], r1[0]);
#pragma unroll
            for (int op = 1; op < 8; op++) {
                t0 = fma2(h0[op], r0[op], t0);
                t1 = fma2(h1[op], r1[op], t1);
            }
            float2 q0 = unpack2(t0), q1 = unpack2(t1);
            float bias0 = q0.x + q0.y;
            float bias1 = q1.x + q1.y;
            // softmax over 16 k: 2 locals x 8 kp lanes (lane bits 0..2)
            float m = fmaxf(bias0, bias1);
            m = fmaxf(m, __shfl_xor_sync(0xffffffffu, m, 1));
            m = fmaxf(m, __shfl_xor_sync(0xffffffffu, m, 2));
            m = fmaxf(m, __shfl_xor_sync(0xffffffffu, m, 4));
            float e0 = __expf(bias0 - m), e1 = __expf(bias1 - m);
            float s = e0 + e1;
            s += __shfl_xor_sync(0xffffffffu, s, 1);
            s += __shfl_xor_sync(0xffffffffu, s, 2);
            s += __shfl_xor_sync(0xffffffffu, s, 4);
            float inv = __fdividef(1.0f, s);
            ull c0 = pack2(e0 * inv), c1 = pack2(e1 * inv);
#pragma unroll
            for (int op = 0; op < 8; op++) {
                acc0[op] = fma2(c0, h0[op], acc0[op]);
                acc1[op] = fma2(c1, h1[op], acc1[op]);
            }
        }
        __syncthreads();   // all reads of Ws done before next STS
    }

    // ---- write this block's partial s [b][k][o] ----
    float* pp = &g_part[((size_t)blockIdx.x * 64 + b) * 256 + (size_t)(2 * kp) * 16];
#pragma unroll
    for (int op = 0; op < 8; op++) {
        float2 v0 = unpack2(acc0[op]);
        float2 v1 = unpack2(acc1[op]);
        pp[2 * op]          = v0.x;
        pp[2 * op + 1]      = v0.y;
        pp[16 + 2 * op]     = v1.x;
        pp[16 + 2 * op + 1] = v1.y;
    }
}

// Reduce partials over NBLK blocks, squash, update route / emit final output.
// grid = 64 (b), block = 256 (tid = k*16 + o).
__global__ void squash_kernel(float scale, int mode, float* __restrict__ out) {
    const int tid = threadIdx.x;
    const int bidx = blockIdx.x;
    const float* p = g_part + (size_t)bidx * 256 + tid;
    float s = 0.f;
#pragma unroll 8
    for (int j = 0; j < NBLK; j++) s += p[(size_t)j * 16384];
    s *= scale;
    // sum of squares over o (lane bits 0..3)
    float s2 = s * s;
    s2 += __shfl_xor_sync(0xffffffffu, s2, 1);
    s2 += __shfl_xor_sync(0xffffffffu, s2, 2);
    s2 += __shfl_xor_sync(0xffffffffu, s2, 4);
    s2 += __shfl_xor_sync(0xffffffffu, s2, 8);
    float sc = s2 / ((1.0f + s2) * sqrtf(s2));
    float v = sc * s;
    int idx = bidx * 256 + tid;
    if (mode == 0)      g_route[idx] = v;        // route = out0
    else if (mode == 1) g_route[idx] += v;       // route = out0 + out1
    else                out[idx] = v;            // final output [B,16,16]
}

extern "C" void kernel_launch(void* const* d_in, const int* in_sizes, int n_in,
                              void* d_out, int out_size) {
    const float* x = (const float*)d_in[0];   // [64, 2048, 8]
    const float* W = (const float*)d_in[1];   // [2048, 16, 8, 16]
    float* out = (float*)d_out;               // [64, 16, 16]
    (void)in_sizes; (void)n_in; (void)out_size;

    pass_kernel<true ><<<NBLK, THREADS>>>(x, W);           // s0 = sum hats (c uniform)
    squash_kernel<<<64, 256>>>(1.0f / 16.0f, 0, out);      // out0 -> route
    pass_kernel<false><<<NBLK, THREADS>>>(x, W);           // bias=hats·out0, s1
    squash_kernel<<<64, 256>>>(1.0f, 1, out);              // route += out1
    pass_kernel<false><<<NBLK, THREADS>>>(x, W);           // bias=hats·(out0+out1), s2
    squash_kernel<<<64, 256>>>(1.0f, 2, out);              // final
}

// round 2
// speedup vs baseline: 1.7048x; 1.7048x over previous
#include <cuda_runtime.h>

// CapsuleBlock: B=64, N=2048, D_in=8, K(N_out)=16, O(D_out)=16, 3 routing iters.
// R2 strategy: compute hats ONCE (K1, fp32 FFMA2), store as bf16 (67MB).
// Routing passes 2/3 are pure streaming kernels over bf16 hats.
// Two-stage reduction for K1 partials; 5 no-op launches so ncu -s 5 hits K1.

#define NBLK   152
#define CHUNK  14          // NBLK*CHUNK = 2128 >= 2048
#define THREADS 512        // K1: thread = (b, kp): b=tid>>3 (64), kp=tid&7

__device__ float g_part [(size_t)NBLK * 16384];          // K1 partials [blk][b][256]
__device__ float g_part2[(size_t)16 * 16384];            // stage-2 partials [g][b][256]
__device__ float g_route[16384];                         // routing vector [b][k][o]
__device__ __align__(16) unsigned short g_hats[(size_t)64 * 2048 * 256]; // bf16 hats

typedef unsigned long long ull;

__device__ __forceinline__ ull pack2(float v) {
    ull r; asm("mov.b64 %0, {%1, %1};" : "=l"(r) : "f"(v)); return r;
}
__device__ __forceinline__ ull fma2(ull a, ull b, ull c) {
    ull d; asm("fma.rn.f32x2 %0, %1, %2, %3;" : "=l"(d) : "l"(a), "l"(b), "l"(c)); return d;
}
__device__ __forceinline__ ull mul2(ull a, ull b) {
    ull d; asm("mul.rn.f32x2 %0, %1, %2;" : "=l"(d) : "l"(a), "l"(b)); return d;
}
__device__ __forceinline__ ull add2(ull a, ull b) {
    ull d; asm("add.rn.f32x2 %0, %1, %2;" : "=l"(d) : "l"(a), "l"(b)); return d;
}
__device__ __forceinline__ float2 unpack2(ull v) {
    float2 r; asm("mov.b64 {%0, %1}, %2;" : "=f"(r.x), "=f"(r.y) : "l"(v)); return r;
}
// pack (lo, hi) floats into bf16x2 word (lo -> low half)
__device__ __forceinline__ unsigned cvtbf2(float lo, float hi) {
    unsigned r; asm("cvt.rn.bf16x2.f32 %0, %1, %2;" : "=r"(r) : "f"(hi), "f"(lo)); return r;
}
// bf16x2 word -> f32x2 (low bf16 -> low f32)
__device__ __forceinline__ ull bf2f2(unsigned w) {
    unsigned lo = w << 16, hi = w & 0xffff0000u;
    ull d; asm("mov.b64 %0, {%1, %2};" : "=l"(d) : "r"(lo), "r"(hi)); return d;
}

__global__ void noop_kernel() {}

// K1: hats = einsum('bd,kdo->bko') per n; acc s0 = sum_n hats; store hats bf16.
__global__ void __launch_bounds__(THREADS, 1)
pass1_kernel(const float* __restrict__ x, const float* __restrict__ W) {
    __shared__ __align__(16) float2 Ws[8][8][16];        // [d][opair][k], 8 KB
    __shared__ float xs[CHUNK][64][8];                   // 28 KB

    const int tid = threadIdx.x;
    const int b  = tid >> 3;
    const int kp = tid & 7;
    const int n0 = blockIdx.x * CHUNK;
    int nmax = 2048 - n0; if (nmax > CHUNK) nmax = CHUNK;

    for (int i = tid; i < nmax * 128; i += THREADS) {
        int ln = i >> 7, r = i & 127, bb = r >> 1, dq = r & 1;
        float4 v = *(const float4*)(x + ((size_t)bb * 2048 + (size_t)(n0 + ln)) * 8 + dq * 4);
        *(float4*)(&xs[ln][bb][dq * 4]) = v;
    }

    const int wk = tid & 15, wt = tid >> 4, wd = wt >> 2, woq = wt & 3;
    const size_t woff = (size_t)wk * 128 + (size_t)wd * 16 + (size_t)woq * 4;
    float4 wreg = make_float4(0.f, 0.f, 0.f, 0.f);
    if (nmax > 0) wreg = *(const float4*)(W + (size_t)n0 * 2048 + woff);

    ull acc0[8], acc1[8];
#pragma unroll
    for (int op = 0; op < 8; op++) { acc0[op] = 0ull; acc1[op] = 0ull; }

    for (int ln = 0; ln < nmax; ln++) {
        Ws[wd][2 * woq    ][wk] = make_float2(wreg.x, wreg.y);
        Ws[wd][2 * woq + 1][wk] = make_float2(wreg.z, wreg.w);
        __syncthreads();
        if (ln + 1 < nmax)
            wreg = *(const float4*)(W + (size_t)(n0 + ln + 1) * 2048 + woff);

        ull h0[8], h1[8];
#pragma unroll
        for (int d = 0; d < 8; d++) {
            ull xd = pack2(xs[ln][b][d]);
#pragma unroll
            for (int op = 0; op < 8; op++) {
                ulonglong2 w = *(const ulonglong2*)&Ws[d][op][2 * kp];
                if (d == 0) { h0[op] = mul2(xd, w.x); h1[op] = mul2(xd, w.y); }
                else        { h0[op] = fma2(xd, w.x, h0[op]); h1[op] = fma2(xd, w.y, h1[op]); }
            }
        }
#pragma unroll
        for (int op = 0; op < 8; op++) {
            acc0[op] = add2(acc0[op], h0[op]);
            acc1[op] = add2(acc1[op], h1[op]);
        }
        // convert + store hats bf16: 64B contiguous per thread
        unsigned s0[8], s1[8];
#pragma unroll
        for (int op = 0; op < 8; op++) {
            float2 a = unpack2(h0[op]); s0[op] = cvtbf2(a.x, a.y);
            float2 c = unpack2(h1[op]); s1[op] = cvtbf2(c.x, c.y);
        }
        unsigned short* hp = g_hats + ((size_t)b * 2048 + (size_t)(n0 + ln)) * 256 + (size_t)(2 * kp) * 16;
        *(uint4*)(hp +  0) = make_uint4(s0[0], s0[1], s0[2], s0[3]);
        *(uint4*)(hp +  8) = make_uint4(s0[4], s0[5], s0[6], s0[7]);
        *(uint4*)(hp + 16) = make_uint4(s1[0], s1[1], s1[2], s1[3]);
        *(uint4*)(hp + 24) = make_uint4(s1[4], s1[5], s1[6], s1[7]);
        __syncthreads();
    }

    float* pp = &g_part[((size_t)blockIdx.x * 64 + b) * 256 + (size_t)(2 * kp) * 16];
#pragma unroll
    for (int op = 0; op < 8; op++) {
        float2 v0 = unpack2(acc0[op]);
        float2 v1 = unpack2(acc1[op]);
        pp[2 * op]          = v0.x;
        pp[2 * op + 1]      = v0.y;
        pp[16 + 2 * op]     = v1.x;
        pp[16 + 2 * op + 1] = v1.y;
    }
}

// Stage-1 reduce of K1 partials: 152 -> 8. grid 512 = (r<8) * (b<64), block 256.
__global__ void red1_kernel() {
    const int r = blockIdx.x >> 6, b = blockIdx.x & 63;
    const int tid = threadIdx.x;
    float s = 0.f;
#pragma unroll
    for (int t = 0; t < 19; t++) {
        int blk = r + 8 * t;
        s += g_part[((size_t)blk * 64 + b) * 256 + tid];
    }
    g_part2[((size_t)r * 64 + b) * 256 + tid] = s;
}

// Routing pass over stored bf16 hats. grid 1024 = (b<64)*(g<16), block 256.
// Warp handles one n at a time: lane l -> k = l>>1, o-half = (l&1)*8.
__global__ void __launch_bounds__(256) route_kernel() {
    const int b = blockIdx.x >> 4, g = blockIdx.x & 15;
    const int w = threadIdx.x >> 5, l = threadIdx.x & 31;
    const int k = l >> 1, oh = (l & 1) * 8;

    ull r[4];
    {
        const float* rp = g_route + ((size_t)b * 16 + k) * 16 + oh;
        ulonglong2 a = *(const ulonglong2*)(rp);
        ulonglong2 c = *(const ulonglong2*)(rp + 4);
        r[0] = a.x; r[1] = a.y; r[2] = c.x; r[3] = c.y;
    }

    ull acc[4] = {0ull, 0ull, 0ull, 0ull};
    const size_t lane_off = (size_t)k * 16 + oh;

#pragma unroll 4
    for (int i = 0; i < 16; i++) {
        int n = g * 128 + i * 8 + w;
        uint4 hv = *(const uint4*)(g_hats + ((size_t)b * 2048 + n) * 256 + lane_off);
        ull h[4];
        h[0] = bf2f2(hv.x); h[1] = bf2f2(hv.y); h[2] = bf2f2(hv.z); h[3] = bf2f2(hv.w);

        ull t = mul2(h[0], r[0]);
        t = fma2(h[1], r[1], t);
        t = fma2(h[2], r[2], t);
        t = fma2(h[3], r[3], t);
        float2 q = unpack2(t);
        float bh = q.x + q.y;
        float bk = bh + __shfl_xor_sync(0xffffffffu, bh, 1);   // bias for this k

        float m = bk;
        m = fmaxf(m, __shfl_xor_sync(0xffffffffu, m, 2));
        m = fmaxf(m, __shfl_xor_sync(0xffffffffu, m, 4));
        m = fmaxf(m, __shfl_xor_sync(0xffffffffu, m, 8));
        m = fmaxf(m, __shfl_xor_sync(0xffffffffu, m, 16));
        float e = __expf(bk - m);
        float s = e;
        s += __shfl_xor_sync(0xffffffffu, s, 2);
        s += __shfl_xor_sync(0xffffffffu, s, 4);
        s += __shfl_xor_sync(0xffffffffu, s, 8);
        s += __shfl_xor_sync(0xffffffffu, s, 16);
        float c = __fdividef(e, s);
        ull c2 = pack2(c);
        acc[0] = fma2(c2, h[0], acc[0]);
        acc[1] = fma2(c2, h[1], acc[1]);
        acc[2] = fma2(c2, h[2], acc[2]);
        acc[3] = fma2(c2, h[3], acc[3]);
    }

    __shared__ ull red[8][32][4];   // 8 KB
#pragma unroll
    for (int j = 0; j < 4; j++) red[w][l][j] = acc[j];
    __syncthreads();
    if (threadIdx.x < 128) {
        const int u = threadIdx.x & 3, ll = threadIdx.x >> 2;
        ull s = red[0][ll][u];
#pragma unroll
        for (int ww = 1; ww < 8; ww++) s = add2(s, red[ww][ll][u]);
        float2 v = unpack2(s);
        const int off = (ll >> 1) * 16 + (ll & 1) * 8 + u * 2;
        float* dst = g_part2 + ((size_t)g * 64 + b) * 256 + off;
        dst[0] = v.x; dst[1] = v.y;
    }
}

// Reduce cnt chunks of g_part2, squash, update route / emit output.
// grid 64 (b), block 256 (k*16+o).
__global__ void squash_kernel(int cnt, float scale, int mode, float* __restrict__ out) {
    const int tid = threadIdx.x;
    const int bidx = blockIdx.x;
    const float* p = g_part2 + (size_t)bidx * 256 + tid;
    float s = 0.f;
#pragma unroll 16
    for (int j = 0; j < cnt; j++) s += p[(size_t)j * 16384];
    s *= scale;
    float s2 = s * s;
    s2 += __shfl_xor_sync(0xffffffffu, s2, 1);
    s2 += __shfl_xor_sync(0xffffffffu, s2, 2);
    s2 += __shfl_xor_sync(0xffffffffu, s2, 4);
    s2 += __shfl_xor_sync(0xffffffffu, s2, 8);
    float sc = s2 / ((1.0f + s2) * sqrtf(s2));
    float v = sc * s;
    int idx = bidx * 256 + tid;
    if (mode == 0)      g_route[idx] = v;
    else if (mode == 1) g_route[idx] += v;
    else                out[idx] = v;
}

extern "C" void kernel_launch(void* const* d_in, const int* in_sizes, int n_in,
                              void* d_out, int out_size) {
    const float* x = (const float*)d_in[0];   // [64, 2048, 8]
    const float* W = (const float*)d_in[1];   // [2048, 16, 8, 16]
    float* out = (float*)d_out;               // [64, 16, 16]
    (void)in_sizes; (void)n_in; (void)out_size;

    // 5 no-op launches so ncu (-s 5 -c 1) profiles pass1_kernel
    for (int i = 0; i < 5; i++) noop_kernel<<<1, 1>>>();

    pass1_kernel<<<NBLK, THREADS>>>(x, W);          // hats (bf16) + s0 partials
    red1_kernel<<<512, 256>>>();                    // 152 -> 8 partials
    squash_kernel<<<64, 256>>>(8, 1.0f / 16.0f, 0, out);   // out0 -> route
    route_kernel<<<1024, 256>>>();                  // s1 partials (16)
    squash_kernel<<<64, 256>>>(16, 1.0f, 1, out);   // route += out1
    route_kernel<<<1024, 256>>>();                  // s2 partials (16)
    squash_kernel<<<64, 256>>>(16, 1.0f, 2, out);   // final output
}